// round 16
// baseline (speedup 1.0000x reference)
#include <cuda_runtime.h>
#include <cstdint>

#define DM   512
#define NH   4
#define HD   128
#define NB   2
#define SEQ  4096
#define MROWS (NB * SEQ)   // 8192

// truncation-bias compensation per product of two truncated tf32 operands
#define COMP 1.000226f

// Scratch (no allocations allowed)
__device__ float g_Q[NB * NH * SEQ * HD];   // [b][h][s][d]
__device__ float g_K[NB * NH * SEQ * HD];   // [b][h][s][d]
__device__ float g_V[NB * NH * SEQ * HD];   // TRANSPOSED: [b][h][d][s]
__device__ float g_A[MROWS * DM];           // attention out, [b][s][h*hd]

// ---------------------------------------------------------------------------
// helpers
// ---------------------------------------------------------------------------
__device__ __forceinline__ uint32_t smem_u32(const void* p) {
    uint32_t a;
    asm("{ .reg .u64 t; cvta.to.shared.u64 t, %1; cvt.u32.u64 %0, t; }"
        : "=r"(a) : "l"(p));
    return a;
}
// D(16x8,f32) += A(16x8,tf32,row) @ B(8x8,tf32,col)
__device__ __forceinline__ void mma_tf32(float* c, const uint32_t* a,
                                         uint32_t b0, uint32_t b1) {
    asm volatile(
        "mma.sync.aligned.m16n8k8.row.col.f32.tf32.tf32.f32 "
        "{%0,%1,%2,%3}, {%4,%5,%6,%7}, {%8,%9}, {%0,%1,%2,%3};"
        : "+f"(c[0]), "+f"(c[1]), "+f"(c[2]), "+f"(c[3])
        : "r"(a[0]), "r"(a[1]), "r"(a[2]), "r"(a[3]), "r"(b0), "r"(b1));
}
__device__ __forceinline__ void cp16(uint32_t saddr, const void* g) {
    asm volatile("cp.async.cg.shared.global [%0], [%1], 16;"
                 :: "r"(saddr), "l"(g));
}
#define CP_COMMIT() asm volatile("cp.async.commit_group;" ::: "memory")
#define CP_WAIT(N)  asm volatile("cp.async.wait_group %0;" :: "n"(N) : "memory")

// ldmatrix x4: lane i supplies smem row addr for matrix i/8, row i%8;
// result reg for matrix m = 32-bit word (lane%4) of row (lane/4).
__device__ __forceinline__ void ldsm4(uint32_t& r0, uint32_t& r1,
                                      uint32_t& r2, uint32_t& r3, uint32_t a) {
    asm volatile("ldmatrix.sync.aligned.m8n8.x4.shared.b16 {%0,%1,%2,%3}, [%4];"
                 : "=r"(r0), "=r"(r1), "=r"(r2), "=r"(r3) : "r"(a));
}

// ---------------------------------------------------------------------------
// Tensor-core projection GEMM: C[8192,512] = X @ W^T + bias.
// CTA tile 128x128, BK=32 double-buffered cp.async, 8 warps (4m x 2n).
// split: 0 flat, 1 split-head [b][h][s][d], 2 split-head transposed [b][h][d][s]
// ---------------------------------------------------------------------------
#define PJ_BUF (128 * 36)
#define PJ_SMEM (4 * PJ_BUF * 4)                // 73728 B

__device__ __forceinline__ void pj_stage(
    const float* __restrict__ X, const float* __restrict__ W,
    uint32_t sx_u, uint32_t sw_u, int m0, int n0, int k0, int buf, int tid)
{
    const uint32_t xb = sx_u + buf * PJ_BUF * 4;
    const uint32_t wb = sw_u + buf * PJ_BUF * 4;
#pragma unroll
    for (int i = 0; i < 4; i++) {
        int idx = tid + i * 256;
        int row = idx >> 3, c4 = (idx & 7) * 4;
        cp16(xb + (row * 36 + c4) * 4, &X[(size_t)(m0 + row) * DM + k0 + c4]);
        cp16(wb + (row * 36 + c4) * 4, &W[(size_t)(n0 + row) * DM + k0 + c4]);
    }
}

__device__ __forceinline__ void gemm_tc_body(
    const float* __restrict__ X, const float* __restrict__ W,
    const float* __restrict__ bias, float* __restrict__ dst, int split,
    uint32_t* sX, uint32_t* sW)
{
    const int m0 = blockIdx.x * 128;
    const int n0 = blockIdx.y * 128;
    const int tid = threadIdx.x;
    const int w = tid >> 5, lane = tid & 31;
    const int gid = lane >> 2, tig = lane & 3;
    const int mw = (w >> 1) * 32;
    const int nw = (w & 1) * 64;
    const uint32_t sx_u = smem_u32(sX), sw_u = smem_u32(sW);

    float acc[2][8][4];
#pragma unroll
    for (int mi = 0; mi < 2; mi++)
#pragma unroll
        for (int ni = 0; ni < 8; ni++)
#pragma unroll
            for (int j = 0; j < 4; j++) acc[mi][ni][j] = 0.f;

    pj_stage(X, W, sx_u, sw_u, m0, n0, 0, 0, tid);
    CP_COMMIT();

    const int T = DM / 32;                      // 16
    for (int ki = 0; ki < T; ki++) {
        if (ki > 0) __syncthreads();
        if (ki + 1 < T) {
            pj_stage(X, W, sx_u, sw_u, m0, n0, (ki + 1) * 32, (ki + 1) & 1, tid);
            CP_COMMIT();
            CP_WAIT(1);
        } else {
            CP_WAIT(0);
        }
        __syncthreads();

        const uint32_t* bX = sX + (ki & 1) * PJ_BUF;
        const uint32_t* bW = sW + (ki & 1) * PJ_BUF;
#pragma unroll
        for (int kk = 0; kk < 4; kk++) {
            uint32_t a[2][4];
#pragma unroll
            for (int mi = 0; mi < 2; mi++) {
                const uint32_t* xr = bX + (mw + mi * 16 + gid) * 36 + kk * 8;
                a[mi][0] = xr[tig];
                a[mi][2] = xr[tig + 4];
                const uint32_t* xr2 = xr + 8 * 36;
                a[mi][1] = xr2[tig];
                a[mi][3] = xr2[tig + 4];
            }
#pragma unroll
            for (int ni = 0; ni < 8; ni++) {
                const uint32_t* wr = bW + (nw + ni * 8 + gid) * 36 + kk * 8;
                uint32_t b0 = wr[tig], b1 = wr[tig + 4];
                mma_tf32(acc[0][ni], a[0], b0, b1);
                mma_tf32(acc[1][ni], a[1], b0, b1);
            }
        }
    }

#pragma unroll
    for (int mi = 0; mi < 2; mi++) {
        int r0 = m0 + mw + mi * 16 + gid;
#pragma unroll
        for (int ni = 0; ni < 8; ni++) {
            int c = n0 + nw + ni * 8 + 2 * tig;
            float bx = bias[c], by = bias[c + 1];
            float x0 = acc[mi][ni][0] * COMP + bx;
            float y0 = acc[mi][ni][1] * COMP + by;
            float x1 = acc[mi][ni][2] * COMP + bx;
            float y1 = acc[mi][ni][3] * COMP + by;
            if (split == 0) {
                *(float2*)&dst[(size_t)r0 * DM + c] = make_float2(x0, y0);
                *(float2*)&dst[(size_t)(r0 + 8) * DM + c] = make_float2(x1, y1);
            } else {
                int h = c >> 7, d = c & (HD - 1);
                int b0r = r0 >> 12, s0 = r0 & (SEQ - 1);
                int r1 = r0 + 8;
                int b1r = r1 >> 12, s1 = r1 & (SEQ - 1);
                if (split == 1) {
                    *(float2*)&dst[(((size_t)(b0r * NH + h)) * SEQ + s0) * HD + d] =
                        make_float2(x0, y0);
                    *(float2*)&dst[(((size_t)(b1r * NH + h)) * SEQ + s1) * HD + d] =
                        make_float2(x1, y1);
                } else {           // transposed [b][h][d][s]
                    size_t p0 = (((size_t)(b0r * NH + h)) * HD + d) * SEQ;
                    size_t p1 = (((size_t)(b1r * NH + h)) * HD + d) * SEQ;
                    dst[p0 + s0] = x0; dst[p0 + SEQ + s0] = y0;
                    dst[p1 + s1] = x1; dst[p1 + SEQ + s1] = y1;
                }
            }
        }
    }
}

__global__ __launch_bounds__(256, 2) void qkv_proj_tc(
    const float* __restrict__ q, const float* __restrict__ k,
    const float* __restrict__ v,
    const float* __restrict__ Wq, const float* __restrict__ bq,
    const float* __restrict__ Wk, const float* __restrict__ bk,
    const float* __restrict__ Wv, const float* __restrict__ bv)
{
    extern __shared__ uint32_t pjw[];
    uint32_t* sX = pjw;
    uint32_t* sW = pjw + 2 * PJ_BUF;
    const int z = blockIdx.z;
    if (z == 0)      gemm_tc_body(q, Wq, bq, g_Q, 1, sX, sW);
    else if (z == 1) gemm_tc_body(k, Wk, bk, g_K, 1, sX, sW);
    else             gemm_tc_body(v, Wv, bv, g_V, 2, sX, sW);
}

__global__ __launch_bounds__(256, 2) void out_proj_tc(
    const float* __restrict__ Wo, const float* __restrict__ bo,
    float* __restrict__ outp)
{
    extern __shared__ uint32_t pjw[];
    uint32_t* sX = pjw;
    uint32_t* sW = pjw + 2 * PJ_BUF;
    gemm_tc_body(g_A, Wo, bo, outp, 0, sX, sW);
}

// ---------------------------------------------------------------------------
// Flash attention (mma.sync tf32 + ldmatrix fragments).
// 256 threads, 128 q-rows/CTA (16/warp), 64-key tiles, cp.async double buffer.
// K smem [key][d] stride 132; V smem [d][key] stride 68 (from transposed g_V);
// P per-warp [16][68].
// ---------------------------------------------------------------------------
#define KT   64
#define KSTR 132
#define VSTR 68
#define PSTR 68
#define KBUF (KT * KSTR)                        // 8448 words
#define VBUF (HD * VSTR)                        // 8704 words
#define PWORDS (16 * PSTR)                      // 1088 words / warp
#define FLASH_SMEM ((2 * KBUF + 2 * VBUF + 8 * PWORDS) * 4)  // 172032 B

__device__ __forceinline__ void fa_stage(
    const float* __restrict__ Kg, const float* __restrict__ Vt,
    uint32_t sk_u, uint32_t sv_u, int k0, int buf, int tid)
{
    const uint32_t kb = sk_u + buf * KBUF * 4;
    const uint32_t vb = sv_u + buf * VBUF * 4;
#pragma unroll
    for (int i = 0; i < 8; i++) {
        int idx = tid + i * 256;
        int krow = idx >> 5, kc = (idx & 31) * 4;
        cp16(kb + (krow * KSTR + kc) * 4, &Kg[(size_t)(k0 + krow) * HD + kc]);
        int vd = idx >> 4, vc = (idx & 15) * 4;
        cp16(vb + (vd * VSTR + vc) * 4, &Vt[(size_t)vd * SEQ + k0 + vc]);
    }
}

__global__ __launch_bounds__(256, 1) void flash_attn_mma()
{
    extern __shared__ uint32_t smw[];
    uint32_t* sK = smw;                         // [2][KT][KSTR]
    uint32_t* sV = sK + 2 * KBUF;               // [2][HD][VSTR]
    uint32_t* sP = sV + 2 * VBUF;               // 8 x [16][PSTR]

    const int tid  = threadIdx.x;
    const int wq   = tid >> 5;
    const int lane = tid & 31;
    const int gid  = lane >> 2;
    const int tig  = lane & 3;
    const int bh = blockIdx.y;
    const int q0 = blockIdx.x * 128;
    const float cscale = 0.08838834764831845f * COMP;  // 1/sqrt(128) * comp(QK)

    const float* Qg = g_Q + (size_t)bh * SEQ * HD;
    const float* Kg = g_K + (size_t)bh * SEQ * HD;
    const float* Vt = g_V + (size_t)bh * HD * SEQ;     // [d][s]
    const uint32_t sk_u = smem_u32(sK), sv_u = smem_u32(sV);
    uint32_t* sPw = sP + wq * PWORDS;
    const uint32_t pw_u = smem_u32(sPw);

    // ldmatrix per-lane byte offsets
    const uint32_t kl  = ((lane & 7) * KSTR + (lane >> 3) * 4) * 4;
    const uint32_t vl  = (((lane >> 4) * 8 + (lane & 7)) * VSTR +
                          ((lane >> 3) & 1) * 4) * 4;
    const uint32_t plm = (((lane & 7) + 8 * ((lane >> 3) & 1)) * PSTR +
                          (lane >> 4) * 4) * 4;

    // prefetch tile 0
    fa_stage(Kg, Vt, sk_u, sv_u, 0, 0, tid);
    CP_COMMIT();

    // Q fragments (raw fp32 bits as tf32)
    uint32_t qa[16][4];
    {
        const float* qr0 = Qg + (size_t)(q0 + wq * 16 + gid) * HD;
        const float* qr1 = qr0 + 8 * HD;
#pragma unroll
        for (int kk = 0; kk < 16; kk++) {
            qa[kk][0] = __float_as_uint(qr0[kk * 8 + tig] * cscale);
            qa[kk][1] = __float_as_uint(qr1[kk * 8 + tig] * cscale);
            qa[kk][2] = __float_as_uint(qr0[kk * 8 + tig + 4] * cscale);
            qa[kk][3] = __float_as_uint(qr1[kk * 8 + tig + 4] * cscale);
        }
    }

    float oacc[16][4];
#pragma unroll
    for (int n = 0; n < 16; n++)
#pragma unroll
        for (int j = 0; j < 4; j++) oacc[n][j] = 0.f;
    float m0 = -1e30f, m1 = -1e30f, l0 = 0.f, l1 = 0.f;

    const int T = SEQ / KT;                     // 64 tiles
    for (int t = 0; t < T; t++) {
        if (t > 0) __syncthreads();
        if (t + 1 < T) {
            fa_stage(Kg, Vt, sk_u, sv_u, (t + 1) * KT, (t + 1) & 1, tid);
            CP_COMMIT();
            CP_WAIT(1);
        } else {
            CP_WAIT(0);
        }
        __syncthreads();

        const uint32_t bKu = sk_u + (t & 1) * KBUF * 4;
        const uint32_t bVu = sv_u + (t & 1) * VBUF * 4;

        // ---- S = Q @ K^T ----
        float sacc[8][4];
#pragma unroll
        for (int n = 0; n < 8; n++) {
            sacc[n][0] = sacc[n][1] = sacc[n][2] = sacc[n][3] = 0.f;
            uint32_t base = bKu + n * (8 * KSTR * 4) + kl;
#pragma unroll
            for (int j = 0; j < 8; j++) {
                uint32_t b0, b1, b2, b3;
                ldsm4(b0, b1, b2, b3, base + j * 64);
                mma_tf32(sacc[n], qa[2 * j], b0, b1);
                mma_tf32(sacc[n], qa[2 * j + 1], b2, b3);
            }
        }

        // ---- online softmax ----
        float mx0 = m0, mx1 = m1;
#pragma unroll
        for (int n = 0; n < 8; n++) {
            mx0 = fmaxf(mx0, fmaxf(sacc[n][0], sacc[n][1]));
            mx1 = fmaxf(mx1, fmaxf(sacc[n][2], sacc[n][3]));
        }
        mx0 = fmaxf(mx0, __shfl_xor_sync(0xffffffffu, mx0, 1));
        mx0 = fmaxf(mx0, __shfl_xor_sync(0xffffffffu, mx0, 2));
        mx1 = fmaxf(mx1, __shfl_xor_sync(0xffffffffu, mx1, 1));
        mx1 = fmaxf(mx1, __shfl_xor_sync(0xffffffffu, mx1, 2));

        const float alpha0 = __expf(m0 - mx0);
        const float alpha1 = __expf(m1 - mx1);
        m0 = mx0; m1 = mx1;

        float sum0 = 0.f, sum1 = 0.f;
#pragma unroll
        for (int n = 0; n < 8; n++) {
            float p00 = __expf(sacc[n][0] - mx0);
            float p01 = __expf(sacc[n][1] - mx0);
            float p10 = __expf(sacc[n][2] - mx1);
            float p11 = __expf(sacc[n][3] - mx1);
            sum0 += p00 + p01;
            sum1 += p10 + p11;
            uint2 w0; w0.x = __float_as_uint(p00); w0.y = __float_as_uint(p01);
            uint2 w1; w1.x = __float_as_uint(p10); w1.y = __float_as_uint(p11);
            *(uint2*)&sPw[gid * PSTR + n * 8 + 2 * tig] = w0;
            *(uint2*)&sPw[(gid + 8) * PSTR + n * 8 + 2 * tig] = w1;
        }
        sum0 += __shfl_xor_sync(0xffffffffu, sum0, 1);
        sum0 += __shfl_xor_sync(0xffffffffu, sum0, 2);
        sum1 += __shfl_xor_sync(0xffffffffu, sum1, 1);
        sum1 += __shfl_xor_sync(0xffffffffu, sum1, 2);
        l0 = l0 * alpha0 + sum0;
        l1 = l1 * alpha1 + sum1;

#pragma unroll
        for (int n = 0; n < 16; n++) {
            oacc[n][0] *= alpha0; oacc[n][1] *= alpha0;
            oacc[n][2] *= alpha1; oacc[n][3] *= alpha1;
        }
        __syncwarp();                           // P visible within warp

        // ---- O += P @ V ----
#pragma unroll
        for (int kk = 0; kk < 8; kk++) {
            uint32_t pa[4];
            ldsm4(pa[0], pa[1], pa[2], pa[3], pw_u + plm + kk * 32);
#pragma unroll
            for (int nj = 0; nj < 8; nj++) {
                uint32_t v0, v1, v2, v3;
                ldsm4(v0, v1, v2, v3,
                      bVu + vl + nj * (16 * VSTR * 4) + kk * 32);
                mma_tf32(oacc[2 * nj], pa, v0, v1);
                mma_tf32(oacc[2 * nj + 1], pa, v2, v3);
            }
        }
    }

    // ---- epilogue ----
    const int b = bh >> 2, h = bh & 3;
    const float inv0 = COMP / l0, inv1 = COMP / l1;   // comp(PV)
    float* a0 = g_A + (size_t)(b * SEQ + q0 + wq * 16 + gid) * DM + h * HD;
    float* a1 = a0 + 8 * DM;
#pragma unroll
    for (int n = 0; n < 16; n++) {
        float2 w0; w0.x = oacc[n][0] * inv0; w0.y = oacc[n][1] * inv0;
        float2 w1; w1.x = oacc[n][2] * inv1; w1.y = oacc[n][3] * inv1;
        *(float2*)&a0[n * 8 + 2 * tig] = w0;
        *(float2*)&a1[n * 8 + 2 * tig] = w1;
    }
}

// ---------------------------------------------------------------------------
extern "C" void kernel_launch(void* const* d_in, const int* in_sizes, int n_in,
                              void* d_out, int out_size)
{
    const float* query = (const float*)d_in[0];
    const float* key   = (const float*)d_in[1];
    const float* value = (const float*)d_in[2];
    const float* Wq = (const float*)d_in[3];
    const float* bq = (const float*)d_in[4];
    const float* Wk = (const float*)d_in[5];
    const float* bk = (const float*)d_in[6];
    const float* Wv = (const float*)d_in[7];
    const float* bv = (const float*)d_in[8];
    const float* Wo = (const float*)d_in[9];
    const float* bo = (const float*)d_in[10];
    float* out = (float*)d_out;

    (void)cudaFuncSetAttribute(flash_attn_mma,
                               cudaFuncAttributeMaxDynamicSharedMemorySize,
                               FLASH_SMEM);
    (void)cudaFuncSetAttribute(qkv_proj_tc,
                               cudaFuncAttributeMaxDynamicSharedMemorySize,
                               PJ_SMEM);
    (void)cudaFuncSetAttribute(out_proj_tc,
                               cudaFuncAttributeMaxDynamicSharedMemorySize,
                               PJ_SMEM);

    dim3 blk(256);
    dim3 gqkv(MROWS / 128, DM / 128, 3);     // 64 x 4 x 3
    qkv_proj_tc<<<gqkv, blk, PJ_SMEM>>>(query, key, value,
                                        Wq, bq, Wk, bk, Wv, bv);

    dim3 ga(SEQ / 128, NB * NH);             // 32 x 8
    flash_attn_mma<<<ga, blk, FLASH_SMEM>>>();

    dim3 go(MROWS / 128, DM / 128);          // 64 x 4
    out_proj_tc<<<go, blk, PJ_SMEM>>>(Wo, bo, out);
}